// round 4
// baseline (speedup 1.0000x reference)
#include <cuda_runtime.h>
#include <stdint.h>
#include <math.h>

// ---------------- problem constants ----------------
#define L_LAYERS 2
#define S_LEN    1024
#define HID      2048
#define NH       16
#define HD       128
#define INTER    5632
#define VOCAB    32000
#define EPS_RMS  1e-5f
#define ATT_SCALE 0.08838834764831845f  // 1/sqrt(128)
#define QKV_N    (3 * HID)    // 6144
#define GU_N     (2 * INTER)  // 11264

// ---------------- GEMM tile config ----------------
#define BM 128
#define BN 128
#define KC 64                      // K elems per stage (int8 -> 64B rows)
#define NSTAGE 4
#define TILEB 8192                 // one 128x64 int8 tile
#define SC_OFF (3 * TILEB)         // scales: 2 groups x 128 floats = 1024B
#define STAGE_BYTES (3 * TILEB + 1024)   // 25600
#define GEMM_SMEM (NSTAGE * STAGE_BYTES) // 102400

// ---------------- scratch (device globals; no allocs allowed) ----------------
__device__ __align__(1024) int8_t g_wq[(size_t)VOCAB * HID];       // quantized weights
__device__ __align__(1024) float  g_wsc[(size_t)64 * VOCAB];       // weight scales [g][N]
__device__ __align__(1024) int8_t g_xh[(size_t)S_LEN * INTER];     // activation hi
__device__ __align__(1024) int8_t g_xl[(size_t)S_LEN * INTER];     // activation lo
__device__ __align__(1024) float  g_sx[S_LEN];                     // activation row scales
__device__ __align__(1024) float  g_h[S_LEN * HID];
__device__ __align__(1024) float  g_a[S_LEN * HID];
__device__ __align__(1024) float  g_ctx[S_LEN * HID];
__device__ __align__(1024) float  g_qkv[(size_t)S_LEN * QKV_N];
__device__ __align__(1024) float  g_gu[(size_t)S_LEN * GU_N];

// ---------------- PTX helpers (sm_80-portable only) ----------------
__device__ __forceinline__ uint32_t smem_u32(const void* p) {
    uint32_t r;
    asm("{ .reg .u64 t; cvta.to.shared.u64 t, %1; cvt.u32.u64 %0, t; }" : "=r"(r) : "l"(p));
    return r;
}
__device__ __forceinline__ void cpa16(uint32_t s, const void* g) {
    asm volatile("cp.async.cg.shared.global [%0], [%1], 16;" :: "r"(s), "l"(g));
}
__device__ __forceinline__ void cpa4(uint32_t s, const void* g) {
    asm volatile("cp.async.ca.shared.global [%0], [%1], 4;" :: "r"(s), "l"(g));
}
__device__ __forceinline__ void ldsm4(uint32_t* r, uint32_t addr) {
    asm volatile("ldmatrix.sync.aligned.m8n8.x4.shared.b16 {%0,%1,%2,%3}, [%4];"
                 : "=r"(r[0]), "=r"(r[1]), "=r"(r[2]), "=r"(r[3]) : "r"(addr));
}
__device__ __forceinline__ void imma16832(int* d, const uint32_t* a, uint32_t b0, uint32_t b1) {
    asm volatile("mma.sync.aligned.m16n8k32.row.col.s32.s8.s8.s32 "
                 "{%0,%1,%2,%3}, {%4,%5,%6,%7}, {%8,%9}, {%10,%11,%12,%13};"
                 : "=r"(d[0]), "=r"(d[1]), "=r"(d[2]), "=r"(d[3])
                 : "r"(a[0]), "r"(a[1]), "r"(a[2]), "r"(a[3]), "r"(b0), "r"(b1),
                   "r"(0), "r"(0), "r"(0), "r"(0));
}
// swizzled smem offset within a 128x64B tile: rows of 64B = 4 x 16B chunks,
// chunk ^= (row>>1)&3  -> conflict-free for cp.async stores and ldmatrix.
__device__ __forceinline__ uint32_t swz(uint32_t tilebase, int row, int ch) {
    return tilebase + (uint32_t)row * 64u + (uint32_t)((ch ^ ((row >> 1) & 3)) << 4);
}

// ---------------- int8 2-level GEMM via mma.sync s8 ----------------
// C[m,n] = sx[m]/128 * sum_g s[g,n] * (128*dot(xh,q) + dot(xl,q))  (+ Res)
// grid = (M/128, N/128), 256 threads, warp tile 64x32 (2x4 warps).
template<bool RES>
__global__ void __launch_bounds__(256) gemm_i8(
        const int8_t* __restrict__ xh, const int8_t* __restrict__ xl,
        const int8_t* __restrict__ qw, const float* __restrict__ sG,
        const float* __restrict__ sx,
        const float* __restrict__ Res, float* __restrict__ C,
        int N, int K) {
    extern __shared__ char smem[];
    const uint32_t sb = smem_u32(smem);
    const int tid = threadIdx.x;
    const int lane = tid & 31;
    const int wid = tid >> 5;
    const int warp_m = wid & 1;
    const int warp_n = wid >> 1;
    const int bm = blockIdx.x * BM;
    const int bn = blockIdx.y * BN;
    const int nst = K / KC;

    const char* baseA = (const char*)xh + (size_t)bm * K;
    const char* baseL = (const char*)xl + (size_t)bm * K;
    const char* baseB = (const char*)qw + (size_t)bn * K;

    const int mat = lane >> 3;
    const int i8r = lane & 7;
    const int mrow_off = ((mat & 1) << 3) + i8r;
    const int ch_off = mat >> 1;

    float facc[4][4][4];
#pragma unroll
    for (int a = 0; a < 4; ++a)
#pragma unroll
        for (int b = 0; b < 4; ++b)
#pragma unroll
            for (int c = 0; c < 4; ++c) facc[a][b][c] = 0.f;

    auto load_stage = [&](int j) {
        const uint32_t stb = sb + (uint32_t)(j & (NSTAGE - 1)) * STAGE_BYTES;
        const size_t koff = (size_t)j * KC;
#pragma unroll
        for (int p = 0; p < 6; ++p) {
            int lin = p * 256 + tid;
            int tile = lin >> 9;
            int row = (lin >> 2) & 127;
            int ch = lin & 3;
            const char* gb = (tile == 0 ? baseA : (tile == 1 ? baseL : baseB));
            cpa16(swz(stb + (uint32_t)tile * TILEB, row, ch),
                  gb + koff + (size_t)row * K + ch * 16);
        }
        // 2 groups x 128 scale floats
        cpa4(stb + SC_OFF + (uint32_t)tid * 4,
             sG + (size_t)(2 * j + (tid >> 7)) * N + bn + (tid & 127));
        asm volatile("cp.async.commit_group;" ::: "memory");
    };

    for (int j = 0; j < 3; ++j) load_stage(j);

    for (int i = 0; i < nst; ++i) {
        int allow = nst - 1 - i; if (allow > 2) allow = 2;
        if (allow == 2)      asm volatile("cp.async.wait_group 2;" ::: "memory");
        else if (allow == 1) asm volatile("cp.async.wait_group 1;" ::: "memory");
        else                 asm volatile("cp.async.wait_group 0;" ::: "memory");
        __syncthreads();
        if (i + 3 < nst) load_stage(i + 3);

        const uint32_t stb = sb + (uint32_t)(i & (NSTAGE - 1)) * STAGE_BYTES;
        const float2* scp_base =
            (const float2*)(smem + (size_t)(i & (NSTAGE - 1)) * STAGE_BYTES + SC_OFF);
#pragma unroll
        for (int g = 0; g < 2; ++g) {
            uint32_t ah[4][4], al[4][4], bq[2][4];
#pragma unroll
            for (int mt = 0; mt < 4; ++mt) {
                int r = warp_m * 64 + mt * 16 + mrow_off;
                ldsm4(ah[mt], swz(stb, r, g * 2 + ch_off));
                ldsm4(al[mt], swz(stb + TILEB, r, g * 2 + ch_off));
            }
#pragma unroll
            for (int nb = 0; nb < 2; ++nb) {
                int r = warp_n * 32 + nb * 16 + mrow_off;
                ldsm4(bq[nb], swz(stb + 2 * TILEB, r, g * 2 + ch_off));
            }
            float2 sc[4];
#pragma unroll
            for (int nt = 0; nt < 4; ++nt)
                sc[nt] = scp_base[(g * 128 + warp_n * 32 + nt * 8 + 2 * (lane & 3)) >> 1];
#pragma unroll
            for (int mt = 0; mt < 4; ++mt)
#pragma unroll
                for (int nt = 0; nt < 4; ++nt) {
                    uint32_t b0 = bq[nt >> 1][nt & 1];
                    uint32_t b1 = bq[nt >> 1][(nt & 1) + 2];
                    int dh[4], dl[4];
                    imma16832(dh, ah[mt], b0, b1);
                    imma16832(dl, al[mt], b0, b1);
                    facc[mt][nt][0] += (float)(dh[0] * 128 + dl[0]) * sc[nt].x;
                    facc[mt][nt][1] += (float)(dh[1] * 128 + dl[1]) * sc[nt].y;
                    facc[mt][nt][2] += (float)(dh[2] * 128 + dl[2]) * sc[nt].x;
                    facc[mt][nt][3] += (float)(dh[3] * 128 + dl[3]) * sc[nt].y;
                }
        }
    }

    // epilogue
    const int r0 = bm + warp_m * 64 + (lane >> 2);
#pragma unroll
    for (int mt = 0; mt < 4; ++mt) {
        float sxa = sx[r0 + mt * 16] * 0.0078125f;       // /128
        float sxb = sx[r0 + mt * 16 + 8] * 0.0078125f;
#pragma unroll
        for (int nt = 0; nt < 4; ++nt) {
            int col = bn + warp_n * 32 + nt * 8 + 2 * (lane & 3);
            size_t o0 = (size_t)(r0 + mt * 16) * N + col;
            size_t o1 = (size_t)(r0 + mt * 16 + 8) * N + col;
            float v0 = facc[mt][nt][0] * sxa, v1 = facc[mt][nt][1] * sxa;
            float v2 = facc[mt][nt][2] * sxb, v3 = facc[mt][nt][3] * sxb;
            if (RES) {
                float2 ra = *(const float2*)(Res + o0);
                float2 rb = *(const float2*)(Res + o1);
                v0 += ra.x; v1 += ra.y; v2 += rb.x; v3 += rb.y;
            }
            *(float2*)(C + o0) = make_float2(v0, v1);
            *(float2*)(C + o1) = make_float2(v2, v3);
        }
    }
}

// ---------------- weight quant: exact int4 sim -> int8 q + scale[g][N] ----------------
// 8 threads per group of 32; float4 loads; packed int8 stores.
__global__ void wquant(const float* __restrict__ w, int8_t* __restrict__ q,
                       float* __restrict__ sG, int ngroups, int gpk, int Ntot, int noff) {
    int t = blockIdx.x * blockDim.x + threadIdx.x;
    int gid = t >> 3, l8 = t & 7;
    if (gid >= ngroups) return;
    size_t base = (size_t)gid * 32 + l8 * 4;
    float4 w4 = *(const float4*)(w + base);
    float a = fmaxf(fmaxf(fabsf(w4.x), fabsf(w4.y)), fmaxf(fabsf(w4.z), fabsf(w4.w)));
#pragma unroll
    for (int off = 4; off; off >>= 1) a = fmaxf(a, __shfl_xor_sync(0xffffffffu, a, off));
    float s = a / 7.0f + 1e-12f;
    float q0 = fminf(fmaxf(rintf(w4.x / s), -8.f), 7.f);
    float q1 = fminf(fmaxf(rintf(w4.y / s), -8.f), 7.f);
    float q2 = fminf(fmaxf(rintf(w4.z / s), -8.f), 7.f);
    float q3 = fminf(fmaxf(rintf(w4.w / s), -8.f), 7.f);
    uint32_t pk = ((uint32_t)(int)q0 & 255u) | (((uint32_t)(int)q1 & 255u) << 8) |
                  (((uint32_t)(int)q2 & 255u) << 16) | (((uint32_t)(int)q3 & 255u) << 24);
    *(uint32_t*)(q + base) = pk;
    if (l8 == 0) {
        int n = gid / gpk, g = gid - n * gpk;
        sG[(size_t)g * Ntot + noff + n] = s;
    }
}

// ---------------- embedding gather ----------------
__global__ void embed_kernel(const int* __restrict__ ids, const float* __restrict__ ew,
                             float* __restrict__ h) {
    int s = blockIdx.x;
    int tok = ids[s];
    const float4* src = (const float4*)(ew + (size_t)tok * HID);
    float4* dst = (float4*)(h + (size_t)s * HID);
    for (int i = threadIdx.x; i < HID / 4; i += blockDim.x) dst[i] = src[i];
}

// ---------------- activation quantization helpers ----------------
__device__ __forceinline__ float block_reduce(float v, bool is_max, float* red, int tid) {
#pragma unroll
    for (int off = 16; off; off >>= 1) {
        float o = __shfl_xor_sync(0xffffffffu, v, off);
        v = is_max ? fmaxf(v, o) : v + o;
    }
    if ((tid & 31) == 0) red[tid >> 5] = v;
    __syncthreads();
    float t = red[0];
#pragma unroll
    for (int i = 1; i < 8; ++i) t = is_max ? fmaxf(t, red[i]) : t + red[i];
    return t;
}

__device__ __forceinline__ void quant_row_from_buf(const float* buf, int ncols, float sxv,
                                                   int8_t* xh, int8_t* xl, size_t obase,
                                                   int tid) {
    float inv = 1.f / sxv;
    for (int i0 = tid * 4; i0 < ncols; i0 += 1024) {
        uint32_t ph = 0, pl = 0;
#pragma unroll
        for (int c = 0; c < 4; ++c) {
            float v = buf[i0 + c];
            float hq = rintf(v * inv);
            float rf = v - hq * sxv;
            float lq = fminf(fmaxf(rintf(rf * 128.f * inv), -128.f), 127.f);
            ph |= ((uint32_t)(int)hq & 255u) << (8 * c);
            pl |= ((uint32_t)(int)lq & 255u) << (8 * c);
        }
        *(uint32_t*)(xh + obase + i0) = ph;
        *(uint32_t*)(xl + obase + i0) = pl;
    }
}

// rmsnorm + 2-level int8 quant
__global__ void rmsnorm_q(const float* __restrict__ x, const float* __restrict__ w,
                          int8_t* __restrict__ xh, int8_t* __restrict__ xl,
                          float* __restrict__ sx) {
    __shared__ float buf[HID];
    __shared__ float red[8];
    __shared__ float bc;
    int row = blockIdx.x, tid = threadIdx.x;
    const float* xr = x + (size_t)row * HID;
    float s = 0.f;
    for (int i = tid; i < HID; i += 256) { float v = xr[i]; buf[i] = v; s += v * v; }
    float tot = block_reduce(s, false, red, tid);
    float r = rsqrtf(tot / (float)HID + EPS_RMS);
    __syncthreads();
    float amax = 0.f;
    for (int i = tid; i < HID; i += 256) {
        float v = buf[i] * r * w[i];
        buf[i] = v;
        amax = fmaxf(amax, fabsf(v));
    }
    float m = block_reduce(amax, true, red, tid);
    if (tid == 0) { float sv = m / 127.f + 1e-30f; bc = sv; sx[row] = sv; }
    __syncthreads();
    quant_row_from_buf(buf, HID, bc, xh, xl, (size_t)row * HID, tid);
}

// plain row quant (for attention context)
__global__ void ctx_quant(const float* __restrict__ src, int8_t* __restrict__ xh,
                          int8_t* __restrict__ xl, float* __restrict__ sx) {
    __shared__ float buf[HID];
    __shared__ float red[8];
    __shared__ float bc;
    int row = blockIdx.x, tid = threadIdx.x;
    const float* xr = src + (size_t)row * HID;
    float amax = 0.f;
    for (int i = tid; i < HID; i += 256) {
        float v = xr[i]; buf[i] = v; amax = fmaxf(amax, fabsf(v));
    }
    float m = block_reduce(amax, true, red, tid);
    if (tid == 0) { float sv = m / 127.f + 1e-30f; bc = sv; sx[row] = sv; }
    __syncthreads();
    quant_row_from_buf(buf, HID, bc, xh, xl, (size_t)row * HID, tid);
}

// SwiGLU + quant: v = up * gate * sigmoid(gate)
__global__ void silu_quant(const float* __restrict__ gu, int8_t* __restrict__ xh,
                           int8_t* __restrict__ xl, float* __restrict__ sx) {
    __shared__ float buf[INTER];
    __shared__ float red[8];
    __shared__ float bc;
    int row = blockIdx.x, tid = threadIdx.x;
    const float* rg = gu + (size_t)row * GU_N;
    float amax = 0.f;
    for (int j = tid; j < INTER; j += 256) {
        float g = rg[j];
        float u = rg[INTER + j];
        float v = u * g / (1.f + expf(-g));
        buf[j] = v;
        amax = fmaxf(amax, fabsf(v));
    }
    float m = block_reduce(amax, true, red, tid);
    if (tid == 0) { float sv = m / 127.f + 1e-30f; bc = sv; sx[row] = sv; }
    __syncthreads();
    quant_row_from_buf(buf, INTER, bc, xh, xl, (size_t)row * INTER, tid);
}

// ---------------- rope (llama half-split), in-place on fused qkv ----------------
__global__ void rope_kernel(float* __restrict__ qkv, const int* __restrict__ pos_ptr) {
    int s = blockIdx.x, h = blockIdx.y, d = threadIdx.x;  // d in [0,64)
    int pos = pos_ptr[0] + s;
    float invf = (float)exp(-((double)(2 * d) / 128.0) * log(10000.0));
    float ang  = (float)pos * invf;
    float cs = (float)cos((double)ang);
    float sn = (float)sin((double)ang);
    size_t base = (size_t)s * QKV_N + h * HD;
    float x1 = qkv[base + d], x2 = qkv[base + d + 64];
    qkv[base + d]      = x1 * cs - x2 * sn;
    qkv[base + d + 64] = x2 * cs + x1 * sn;
    size_t kb = base + HID;
    x1 = qkv[kb + d]; x2 = qkv[kb + d + 64];
    qkv[kb + d]      = x1 * cs - x2 * sn;
    qkv[kb + d + 64] = x2 * cs + x1 * sn;
}

// ---------------- flash attention, fp32, 64q x 32k tiles -> fp32 ctx ----------------
__global__ void __launch_bounds__(256) attn_kernel(const float* __restrict__ qkv,
                                                   float* __restrict__ ctx,
                                                   const int* __restrict__ pos_ptr) {
    __shared__ float Ks[32 * 129];
    __shared__ float Vs[32 * 129];
    __shared__ float Ps[64 * 33];
    const int h = blockIdx.x;
    const int qt = blockIdx.y;
    const int tid = threadIdx.x;
    const int r = tid >> 2;
    const int c = tid & 3;
    const int pid = pos_ptr[0];
    const int s = qt * 64 + r;
    const int pos = pid + s;

    float qreg[32], o[32];
    const float* qp = qkv + (size_t)s * QKV_N + h * HD + c * 32;
#pragma unroll
    for (int i = 0; i < 32; ++i) { qreg[i] = qp[(i + 8 * c) & 31]; o[i] = 0.f; }
    float m = -1e30f, l = 0.f;

    int maxpos = pid + qt * 64 + 63;
    int ntiles = maxpos / 32 + 1;
    if (ntiles > S_LEN / 32) ntiles = S_LEN / 32;

    for (int jt = 0; jt < ntiles; ++jt) {
        __syncthreads();
        for (int idx = tid; idx < 32 * 128; idx += 256) {
            int row = idx >> 7, col = idx & 127;
            size_t g = (size_t)(jt * 32 + row) * QKV_N + h * HD + col;
            Ks[row * 129 + col] = qkv[g + HID];
            Vs[row * 129 + col] = qkv[g + 2 * HID];
        }
        __syncthreads();

        float tmax = -1e30f;
        for (int j = 0; j < 32; ++j) {
            const float* kr = &Ks[j * 129 + c * 32];
            float p = 0.f;
#pragma unroll
            for (int i = 0; i < 32; ++i) p += qreg[i] * kr[(i + 8 * c) & 31];
            p += __shfl_xor_sync(0xffffffffu, p, 1);
            p += __shfl_xor_sync(0xffffffffu, p, 2);
            float val = ((jt * 32 + j) <= pos) ? p * ATT_SCALE : -1e30f;
            tmax = fmaxf(tmax, val);
            if ((j & 3) == c) Ps[r * 33 + j] = val;
        }
        __syncwarp();
        float mnew = fmaxf(m, tmax);
        float sf = expf(m - mnew);
        float tsum = 0.f;
#pragma unroll
        for (int jj = 0; jj < 8; ++jj) {
            int j = jj * 4 + c;
            float e = expf(Ps[r * 33 + j] - mnew);
            Ps[r * 33 + j] = e;
            tsum += e;
        }
        tsum += __shfl_xor_sync(0xffffffffu, tsum, 1);
        tsum += __shfl_xor_sync(0xffffffffu, tsum, 2);
        __syncwarp();
        l = l * sf + tsum;
        m = mnew;
#pragma unroll
        for (int i = 0; i < 32; ++i) o[i] *= sf;
        for (int j = 0; j < 32; ++j) {
            float pv = Ps[r * 33 + j];
            const float* vr = &Vs[j * 129 + c * 32];
#pragma unroll
            for (int i = 0; i < 32; ++i) o[i] += pv * vr[(i + 8 * c) & 31];
        }
    }
    float inv = 1.f / l;
    float* cp = ctx + (size_t)s * HID + h * HD + c * 32;
#pragma unroll
    for (int i = 0; i < 32; ++i) cp[(i + 8 * c) & 31] = o[i] * inv;
}

// ---------------- host orchestration ----------------
static void wq(const float* w, int8_t* q, float* sG, int Nsub, int K, int Ntot, int noff) {
    int ngroups = Nsub * (K / 32);
    int threads = ngroups * 8;
    wquant<<<(threads + 255) / 256, 256>>>(w, q, sG, ngroups, K / 32, Ntot, noff);
}

extern "C" void kernel_launch(void* const* d_in, const int* in_sizes, int n_in,
                              void* d_out, int out_size) {
    const int*   input_ids = (const int*)d_in[0];
    const int*   pos_id    = (const int*)d_in[3];
    const float* embed_w   = (const float*)d_in[4];
    const float* in_ln_w   = (const float*)d_in[5];
    const float* post_ln_w = (const float*)d_in[6];
    const float* final_ln  = (const float*)d_in[7];
    const float* q_w       = (const float*)d_in[8];
    const float* k_w       = (const float*)d_in[9];
    const float* v_w       = (const float*)d_in[10];
    const float* o_w       = (const float*)d_in[11];
    const float* gate_w    = (const float*)d_in[12];
    const float* up_w      = (const float*)d_in[13];
    const float* down_w    = (const float*)d_in[14];
    const float* lm_head_w = (const float*)d_in[15];
    float* out = (float*)d_out;

    int8_t *p_wq, *p_xh, *p_xl;
    float *p_wsc, *p_sx, *p_h, *p_a, *p_ctx, *p_qkv, *p_gu;
    cudaGetSymbolAddress((void**)&p_wq, g_wq);
    cudaGetSymbolAddress((void**)&p_wsc, g_wsc);
    cudaGetSymbolAddress((void**)&p_xh, g_xh);
    cudaGetSymbolAddress((void**)&p_xl, g_xl);
    cudaGetSymbolAddress((void**)&p_sx, g_sx);
    cudaGetSymbolAddress((void**)&p_h, g_h);
    cudaGetSymbolAddress((void**)&p_a, g_a);
    cudaGetSymbolAddress((void**)&p_ctx, g_ctx);
    cudaGetSymbolAddress((void**)&p_qkv, g_qkv);
    cudaGetSymbolAddress((void**)&p_gu, g_gu);

    cudaFuncSetAttribute(gemm_i8<false>, cudaFuncAttributeMaxDynamicSharedMemorySize, GEMM_SMEM);
    cudaFuncSetAttribute(gemm_i8<true>,  cudaFuncAttributeMaxDynamicSharedMemorySize, GEMM_SMEM);

    const size_t wsq = (size_t)HID * HID;
    const size_t wsg = (size_t)INTER * HID;

    embed_kernel<<<S_LEN, 256>>>(input_ids, embed_w, p_h);

    for (int l = 0; l < L_LAYERS; ++l) {
        rmsnorm_q<<<S_LEN, 256>>>(p_h, in_ln_w + l * HID, p_xh, p_xl, p_sx);

        // fused QKV
        wq(q_w + l * wsq, p_wq,                    p_wsc, HID, HID, QKV_N, 0);
        wq(k_w + l * wsq, p_wq + wsq,              p_wsc, HID, HID, QKV_N, HID);
        wq(v_w + l * wsq, p_wq + 2 * wsq,          p_wsc, HID, HID, QKV_N, 2 * HID);
        gemm_i8<false><<<dim3(S_LEN / BM, QKV_N / BN), 256, GEMM_SMEM>>>(
            p_xh, p_xl, p_wq, p_wsc, p_sx, nullptr, p_qkv, QKV_N, HID);

        rope_kernel<<<dim3(S_LEN, NH), 64>>>(p_qkv, pos_id);
        attn_kernel<<<dim3(NH, S_LEN / 64), 256>>>(p_qkv, p_ctx, pos_id);
        ctx_quant<<<S_LEN, 256>>>(p_ctx, p_xh, p_xl, p_sx);

        // O-proj + residual
        wq(o_w + l * wsq, p_wq, p_wsc, HID, HID, HID, 0);
        gemm_i8<true><<<dim3(S_LEN / BM, HID / BN), 256, GEMM_SMEM>>>(
            p_xh, p_xl, p_wq, p_wsc, p_sx, p_h, p_a, HID, HID);

        rmsnorm_q<<<S_LEN, 256>>>(p_a, post_ln_w + l * HID, p_xh, p_xl, p_sx);

        // fused gate|up
        wq(gate_w + l * wsg, p_wq,       p_wsc, INTER, HID, GU_N, 0);
        wq(up_w   + l * wsg, p_wq + wsg, p_wsc, INTER, HID, GU_N, INTER);
        gemm_i8<false><<<dim3(S_LEN / BM, GU_N / BN), 256, GEMM_SMEM>>>(
            p_xh, p_xl, p_wq, p_wsc, p_sx, nullptr, p_gu, GU_N, HID);

        silu_quant<<<S_LEN, 256>>>(p_gu, p_xh, p_xl, p_sx);

        // down-proj + residual
        wq(down_w + l * wsg, p_wq, p_wsc, HID, INTER, HID, 0);
        gemm_i8<true><<<dim3(S_LEN / BM, HID / BN), 256, GEMM_SMEM>>>(
            p_xh, p_xl, p_wq, p_wsc, p_sx, p_a, p_h, HID, INTER);
    }

    rmsnorm_q<<<S_LEN, 256>>>(p_h, final_ln, p_xh, p_xl, p_sx);
    wq(lm_head_w, p_wq, p_wsc, VOCAB, HID, VOCAB, 0);
    gemm_i8<false><<<dim3(S_LEN / BM, VOCAB / BN), 256, GEMM_SMEM>>>(
        p_xh, p_xl, p_wq, p_wsc, p_sx, nullptr, out, VOCAB, HID);
}

// round 5
// speedup vs baseline: 1.8940x; 1.8940x over previous
#include <cuda_runtime.h>
#include <cuda_fp16.h>
#include <stdint.h>
#include <math.h>

// ---------------- problem constants ----------------
#define L_LAYERS 2
#define S_LEN    1024
#define HID      2048
#define NH       16
#define HD       128
#define INTER    5632
#define VOCAB    32000
#define EPS_RMS  1e-5f
#define ATT_SCALE 0.08838834764831845f  // 1/sqrt(128)
#define QKV_N    (3 * HID)    // 6144
#define GU_N     (2 * INTER)  // 11264

// ---------------- GEMM tile config ----------------
#define BM 128
#define BN 128
#define KC 64                      // K elems per stage (fp16 -> 128B rows)
#define NSTAGE 4
#define TILEB 16384                // one 128x64 fp16 tile (128 rows x 128B)
#define STAGE_BYTES (3 * TILEB)    // A, Bh, Bl = 49152
#define GEMM_SMEM (NSTAGE * STAGE_BYTES)   // 196608

// ---------------- scratch (device globals; no allocs allowed) ----------------
__device__ __align__(1024) __half g_wh[(size_t)VOCAB * HID];   // weight hi
__device__ __align__(1024) __half g_wl[(size_t)VOCAB * HID];   // weight lo
__device__ __align__(1024) __half g_x[(size_t)S_LEN * INTER];  // activations fp16
__device__ __align__(1024) float  g_h[S_LEN * HID];
__device__ __align__(1024) float  g_a[S_LEN * HID];
__device__ __align__(1024) float  g_qkv[(size_t)S_LEN * QKV_N];
__device__ __align__(1024) float  g_gu[(size_t)S_LEN * GU_N];

// ---------------- PTX helpers (sm_80-portable only) ----------------
__device__ __forceinline__ uint32_t smem_u32(const void* p) {
    uint32_t r;
    asm("{ .reg .u64 t; cvta.to.shared.u64 t, %1; cvt.u32.u64 %0, t; }" : "=r"(r) : "l"(p));
    return r;
}
__device__ __forceinline__ void cpa16(uint32_t s, const void* g) {
    asm volatile("cp.async.cg.shared.global [%0], [%1], 16;" :: "r"(s), "l"(g));
}
__device__ __forceinline__ void ldsm4(uint32_t* r, uint32_t addr) {
    asm volatile("ldmatrix.sync.aligned.m8n8.x4.shared.b16 {%0,%1,%2,%3}, [%4];"
                 : "=r"(r[0]), "=r"(r[1]), "=r"(r[2]), "=r"(r[3]) : "r"(addr));
}
__device__ __forceinline__ void mma16816(float* d, const uint32_t* a, uint32_t b0, uint32_t b1) {
    asm volatile("mma.sync.aligned.m16n8k16.row.col.f32.f16.f16.f32 "
                 "{%0,%1,%2,%3}, {%4,%5,%6,%7}, {%8,%9}, {%0,%1,%2,%3};"
                 : "+f"(d[0]), "+f"(d[1]), "+f"(d[2]), "+f"(d[3])
                 : "r"(a[0]), "r"(a[1]), "r"(a[2]), "r"(a[3]), "r"(b0), "r"(b1));
}
// swizzled smem offset within a 128x128B tile: 8 chunks of 16B per row,
// chunk ^= (row & 7) -> conflict-free for cp.async stores and ldmatrix reads.
__device__ __forceinline__ uint32_t swz(uint32_t tilebase, int row, int ch) {
    return tilebase + (uint32_t)row * 128u + (uint32_t)((ch ^ (row & 7)) << 4);
}

// ---------------- fp16 2-pass GEMM via mma.sync ----------------
// C[M,N] = A[M,K] * (Bh+Bl)[N,K]^T (+ Res), fp32 accum.
// grid = (M/128, N/128), 256 threads. Warp tile 64x32 (warps 2x4 over M,N).
template<bool RES>
__global__ void __launch_bounds__(256) gemm_fp16(
        const __half* __restrict__ A,
        const __half* __restrict__ Bh, const __half* __restrict__ Bl,
        const float* __restrict__ Res, float* __restrict__ C,
        int N, int K) {
    extern __shared__ char smem[];
    const uint32_t sb = smem_u32(smem);
    const int tid = threadIdx.x;
    const int lane = tid & 31;
    const int wid = tid >> 5;
    const int warp_m = wid & 1;
    const int warp_n = wid >> 1;
    const int bm = blockIdx.x * BM;
    const int bn = blockIdx.y * BN;
    const int nst = K / KC;
    const size_t rowb = (size_t)K * 2;

    const char* baseA = (const char*)A  + (size_t)bm * rowb;
    const char* baseH = (const char*)Bh + (size_t)bn * rowb;
    const char* baseL = (const char*)Bl + (size_t)bn * rowb;

    const int mat = lane >> 3;
    const int i8r = lane & 7;
    const int mrow_off = ((mat & 1) << 3) + i8r;   // 0..15
    const int ch_off = mat >> 1;                   // 0 or 1

    float acc[4][4][4];
#pragma unroll
    for (int a = 0; a < 4; ++a)
#pragma unroll
        for (int b = 0; b < 4; ++b)
#pragma unroll
            for (int c = 0; c < 4; ++c) acc[a][b][c] = 0.f;

    auto load_stage = [&](int j) {
        const uint32_t stb = sb + (uint32_t)(j & (NSTAGE - 1)) * STAGE_BYTES;
        const size_t koff = (size_t)j * 128;   // KC*2 bytes
#pragma unroll
        for (int p = 0; p < 12; ++p) {
            int lin = p * 256 + tid;           // 0..3071
            int tile = lin >> 10;              // 0:A 1:Bh 2:Bl
            int wt = lin & 1023;
            int row = wt >> 3, ch = wt & 7;
            const char* gb = (tile == 0 ? baseA : (tile == 1 ? baseH : baseL));
            cpa16(swz(stb + (uint32_t)tile * TILEB, row, ch),
                  gb + koff + (size_t)row * rowb + ch * 16);
        }
        asm volatile("cp.async.commit_group;" ::: "memory");
    };

    for (int j = 0; j < 3; ++j) load_stage(j);

    for (int i = 0; i < nst; ++i) {
        int allow = nst - 1 - i; if (allow > 2) allow = 2;
        if (allow == 2)      asm volatile("cp.async.wait_group 2;" ::: "memory");
        else if (allow == 1) asm volatile("cp.async.wait_group 1;" ::: "memory");
        else                 asm volatile("cp.async.wait_group 0;" ::: "memory");
        __syncthreads();
        if (i + 3 < nst) load_stage(i + 3);

        const uint32_t stb = sb + (uint32_t)(i & (NSTAGE - 1)) * STAGE_BYTES;
#pragma unroll
        for (int h = 0; h < 4; ++h) {          // 4 x k16 within KC=64
            uint32_t af[4][4], bh[2][4], bl[2][4];
#pragma unroll
            for (int mt = 0; mt < 4; ++mt) {
                int r = warp_m * 64 + mt * 16 + mrow_off;
                ldsm4(af[mt], swz(stb, r, h * 2 + ch_off));
            }
#pragma unroll
            for (int nb = 0; nb < 2; ++nb) {
                int r = warp_n * 32 + nb * 16 + mrow_off;
                ldsm4(bh[nb], swz(stb + TILEB,     r, h * 2 + ch_off));
                ldsm4(bl[nb], swz(stb + 2 * TILEB, r, h * 2 + ch_off));
            }
#pragma unroll
            for (int mt = 0; mt < 4; ++mt)
#pragma unroll
                for (int nt = 0; nt < 4; ++nt) {
                    int np = nt >> 1, sub = nt & 1;
                    float* d = acc[mt][nt];
                    mma16816(d, af[mt], bh[np][sub], bh[np][sub + 2]);  // A*Bh
                    mma16816(d, af[mt], bl[np][sub], bl[np][sub + 2]);  // A*Bl
                }
        }
    }

    // epilogue
#pragma unroll
    for (int mt = 0; mt < 4; ++mt)
#pragma unroll
        for (int nt = 0; nt < 4; ++nt) {
            int row = bm + warp_m * 64 + mt * 16 + (lane >> 2);
            int col = bn + warp_n * 32 + nt * 8 + ((lane & 3) << 1);
            float* d = acc[mt][nt];
            size_t o0 = (size_t)row * N + col;
            size_t o1 = (size_t)(row + 8) * N + col;
            if (RES) {
                d[0] += Res[o0]; d[1] += Res[o0 + 1];
                d[2] += Res[o1]; d[3] += Res[o1 + 1];
            }
            *(float2*)(C + o0) = make_float2(d[0], d[1]);
            *(float2*)(C + o1) = make_float2(d[2], d[3]);
        }
}

// ---------------- weight quant: exact int4 sim -> fp16 hi/lo ----------------
// 8 threads per group of 32 along K; float4 loads, half2 stores.
__global__ void wquant_h(const float* __restrict__ w, __half* __restrict__ oh,
                         __half* __restrict__ ol, int ngroups) {
    int t = blockIdx.x * blockDim.x + threadIdx.x;
    int gid = t >> 3, l8 = t & 7;
    if (gid >= ngroups) return;
    size_t base = (size_t)gid * 32 + l8 * 4;
    float4 w4 = *(const float4*)(w + base);
    float a = fmaxf(fmaxf(fabsf(w4.x), fabsf(w4.y)), fmaxf(fabsf(w4.z), fabsf(w4.w)));
#pragma unroll
    for (int off = 4; off; off >>= 1) a = fmaxf(a, __shfl_xor_sync(0xffffffffu, a, off));
    float s = a / 7.0f + 1e-12f;
    float v[4];
    v[0] = fminf(fmaxf(rintf(w4.x / s), -8.f), 7.f) * s;
    v[1] = fminf(fmaxf(rintf(w4.y / s), -8.f), 7.f) * s;
    v[2] = fminf(fmaxf(rintf(w4.z / s), -8.f), 7.f) * s;
    v[3] = fminf(fmaxf(rintf(w4.w / s), -8.f), 7.f) * s;
    __half h[4], l[4];
#pragma unroll
    for (int c = 0; c < 4; ++c) {
        h[c] = __float2half(v[c]);
        l[c] = __float2half(v[c] - __half2float(h[c]));
    }
    *(__half2*)(oh + base)     = __halves2half2(h[0], h[1]);
    *(__half2*)(oh + base + 2) = __halves2half2(h[2], h[3]);
    *(__half2*)(ol + base)     = __halves2half2(l[0], l[1]);
    *(__half2*)(ol + base + 2) = __halves2half2(l[2], l[3]);
}

// ---------------- embedding gather ----------------
__global__ void embed_kernel(const int* __restrict__ ids, const float* __restrict__ ew,
                             float* __restrict__ h) {
    int s = blockIdx.x;
    int tok = ids[s];
    const float4* src = (const float4*)(ew + (size_t)tok * HID);
    float4* dst = (float4*)(h + (size_t)s * HID);
    for (int i = threadIdx.x; i < HID / 4; i += blockDim.x) dst[i] = src[i];
}

// ---------------- rmsnorm -> fp16 ----------------
__global__ void rmsnorm_h(const float* __restrict__ x, const float* __restrict__ w,
                          __half* __restrict__ o) {
    int row = blockIdx.x;
    const float* xr = x + (size_t)row * HID;
    float s = 0.f;
    for (int i = threadIdx.x; i < HID; i += 256) { float v = xr[i]; s += v * v; }
#pragma unroll
    for (int off = 16; off; off >>= 1) s += __shfl_xor_sync(0xffffffffu, s, off);
    __shared__ float red[8];
    __shared__ float rtot;
    if ((threadIdx.x & 31) == 0) red[threadIdx.x >> 5] = s;
    __syncthreads();
    if (threadIdx.x == 0) {
        float t = 0.f;
#pragma unroll
        for (int i = 0; i < 8; ++i) t += red[i];
        rtot = rsqrtf(t / (float)HID + EPS_RMS);
    }
    __syncthreads();
    float r = rtot;
    size_t base = (size_t)row * HID;
    for (int i = threadIdx.x; i < HID; i += 256)
        o[base + i] = __float2half(xr[i] * r * w[i]);
}

// ---------------- rope (llama half-split), in-place on fused qkv ----------------
__global__ void rope_kernel(float* __restrict__ qkv, const int* __restrict__ pos_ptr) {
    int s = blockIdx.x, h = blockIdx.y, d = threadIdx.x;  // d in [0,64)
    int pos = pos_ptr[0] + s;
    float invf = (float)exp(-((double)(2 * d) / 128.0) * log(10000.0));
    float ang  = (float)pos * invf;
    float cs = (float)cos((double)ang);
    float sn = (float)sin((double)ang);
    size_t base = (size_t)s * QKV_N + h * HD;
    float x1 = qkv[base + d], x2 = qkv[base + d + 64];
    qkv[base + d]      = x1 * cs - x2 * sn;
    qkv[base + d + 64] = x2 * cs + x1 * sn;
    size_t kb = base + HID;
    x1 = qkv[kb + d]; x2 = qkv[kb + d + 64];
    qkv[kb + d]      = x1 * cs - x2 * sn;
    qkv[kb + d + 64] = x2 * cs + x1 * sn;
}

// ---------------- flash attention, fp32, 64q x 32k tiles; out -> fp16 ----------------
__global__ void __launch_bounds__(256) attn_kernel(const float* __restrict__ qkv,
                                                   __half* __restrict__ ctx,
                                                   const int* __restrict__ pos_ptr) {
    __shared__ float Ks[32 * 129];
    __shared__ float Vs[32 * 129];
    __shared__ float Ps[64 * 33];
    const int h = blockIdx.x;
    const int qt = blockIdx.y;
    const int tid = threadIdx.x;
    const int r = tid >> 2;
    const int c = tid & 3;
    const int pid = pos_ptr[0];
    const int s = qt * 64 + r;
    const int pos = pid + s;

    float qreg[32], o[32];
    const float* qp = qkv + (size_t)s * QKV_N + h * HD + c * 32;
#pragma unroll
    for (int i = 0; i < 32; ++i) { qreg[i] = qp[(i + 8 * c) & 31]; o[i] = 0.f; }
    float m = -1e30f, l = 0.f;

    int maxpos = pid + qt * 64 + 63;
    int ntiles = maxpos / 32 + 1;
    if (ntiles > S_LEN / 32) ntiles = S_LEN / 32;

    for (int jt = 0; jt < ntiles; ++jt) {
        __syncthreads();
        for (int idx = tid; idx < 32 * 128; idx += 256) {
            int row = idx >> 7, col = idx & 127;
            size_t g = (size_t)(jt * 32 + row) * QKV_N + h * HD + col;
            Ks[row * 129 + col] = qkv[g + HID];
            Vs[row * 129 + col] = qkv[g + 2 * HID];
        }
        __syncthreads();

        float tmax = -1e30f;
        for (int j = 0; j < 32; ++j) {
            const float* kr = &Ks[j * 129 + c * 32];
            float p = 0.f;
#pragma unroll
            for (int i = 0; i < 32; ++i) p += qreg[i] * kr[(i + 8 * c) & 31];
            p += __shfl_xor_sync(0xffffffffu, p, 1);
            p += __shfl_xor_sync(0xffffffffu, p, 2);
            float val = ((jt * 32 + j) <= pos) ? p * ATT_SCALE : -1e30f;
            tmax = fmaxf(tmax, val);
            if ((j & 3) == c) Ps[r * 33 + j] = val;
        }
        __syncwarp();
        float mnew = fmaxf(m, tmax);
        float sf = expf(m - mnew);
        float tsum = 0.f;
#pragma unroll
        for (int jj = 0; jj < 8; ++jj) {
            int j = jj * 4 + c;
            float e = expf(Ps[r * 33 + j] - mnew);
            Ps[r * 33 + j] = e;
            tsum += e;
        }
        tsum += __shfl_xor_sync(0xffffffffu, tsum, 1);
        tsum += __shfl_xor_sync(0xffffffffu, tsum, 2);
        __syncwarp();
        l = l * sf + tsum;
        m = mnew;
#pragma unroll
        for (int i = 0; i < 32; ++i) o[i] *= sf;
        for (int j = 0; j < 32; ++j) {
            float pv = Ps[r * 33 + j];
            const float* vr = &Vs[j * 129 + c * 32];
#pragma unroll
            for (int i = 0; i < 32; ++i) o[i] += pv * vr[(i + 8 * c) & 31];
        }
    }
    float inv = 1.f / l;
    size_t cbase = (size_t)s * HID + h * HD + c * 32;
#pragma unroll
    for (int i = 0; i < 32; ++i)
        ctx[cbase + ((i + 8 * c) & 31)] = __float2half(o[i] * inv);
}

// ---------------- SwiGLU: u = up * gate * sigmoid(gate) -> fp16 ----------------
__global__ void silu_h(const float* __restrict__ gu, __half* __restrict__ o) {
    int s = blockIdx.x;
    const float* row = gu + (size_t)s * GU_N;
    size_t ob = (size_t)s * INTER;
    for (int j = threadIdx.x; j < INTER; j += 256) {
        float g = row[j];
        float u = row[INTER + j];
        o[ob + j] = __float2half(u * g / (1.f + expf(-g)));
    }
}

// ---------------- host orchestration ----------------
static void wq(const float* w, __half* dh, __half* dl, size_t nelem) {
    int ngroups = (int)(nelem / 32);
    int threads = ngroups * 8;
    wquant_h<<<(threads + 255) / 256, 256>>>(w, dh, dl, ngroups);
}

extern "C" void kernel_launch(void* const* d_in, const int* in_sizes, int n_in,
                              void* d_out, int out_size) {
    const int*   input_ids = (const int*)d_in[0];
    const int*   pos_id    = (const int*)d_in[3];
    const float* embed_w   = (const float*)d_in[4];
    const float* in_ln_w   = (const float*)d_in[5];
    const float* post_ln_w = (const float*)d_in[6];
    const float* final_ln  = (const float*)d_in[7];
    const float* q_w       = (const float*)d_in[8];
    const float* k_w       = (const float*)d_in[9];
    const float* v_w       = (const float*)d_in[10];
    const float* o_w       = (const float*)d_in[11];
    const float* gate_w    = (const float*)d_in[12];
    const float* up_w      = (const float*)d_in[13];
    const float* down_w    = (const float*)d_in[14];
    const float* lm_head_w = (const float*)d_in[15];
    float* out = (float*)d_out;

    __half *p_wh, *p_wl, *p_x;
    float *p_h, *p_a, *p_qkv, *p_gu;
    cudaGetSymbolAddress((void**)&p_wh, g_wh);
    cudaGetSymbolAddress((void**)&p_wl, g_wl);
    cudaGetSymbolAddress((void**)&p_x, g_x);
    cudaGetSymbolAddress((void**)&p_h, g_h);
    cudaGetSymbolAddress((void**)&p_a, g_a);
    cudaGetSymbolAddress((void**)&p_qkv, g_qkv);
    cudaGetSymbolAddress((void**)&p_gu, g_gu);

    cudaFuncSetAttribute(gemm_fp16<false>, cudaFuncAttributeMaxDynamicSharedMemorySize, GEMM_SMEM);
    cudaFuncSetAttribute(gemm_fp16<true>,  cudaFuncAttributeMaxDynamicSharedMemorySize, GEMM_SMEM);

    const size_t wsq = (size_t)HID * HID;
    const size_t wsg = (size_t)INTER * HID;

    embed_kernel<<<S_LEN, 256>>>(input_ids, embed_w, p_h);

    for (int l = 0; l < L_LAYERS; ++l) {
        rmsnorm_h<<<S_LEN, 256>>>(p_h, in_ln_w + l * HID, p_x);

        // fused QKV: dequant q|k|v contiguously, one N=6144 GEMM
        wq(q_w + l * wsq, p_wh,           p_wl,           wsq);
        wq(k_w + l * wsq, p_wh + wsq,     p_wl + wsq,     wsq);
        wq(v_w + l * wsq, p_wh + 2 * wsq, p_wl + 2 * wsq, wsq);
        gemm_fp16<false><<<dim3(S_LEN / BM, QKV_N / BN), 256, GEMM_SMEM>>>(
            p_x, p_wh, p_wl, nullptr, p_qkv, QKV_N, HID);

        rope_kernel<<<dim3(S_LEN, NH), 64>>>(p_qkv, pos_id);
        attn_kernel<<<dim3(NH, S_LEN / 64), 256>>>(p_qkv, p_x, pos_id);

        // O-proj + residual
        wq(o_w + l * wsq, p_wh, p_wl, wsq);
        gemm_fp16<true><<<dim3(S_LEN / BM, HID / BN), 256, GEMM_SMEM>>>(
            p_x, p_wh, p_wl, p_h, p_a, HID, HID);

        rmsnorm_h<<<S_LEN, 256>>>(p_a, post_ln_w + l * HID, p_x);

        // fused gate|up: one N=11264 GEMM
        wq(gate_w + l * wsg, p_wh,       p_wl,       wsg);
        wq(up_w   + l * wsg, p_wh + wsg, p_wl + wsg, wsg);
        gemm_fp16<false><<<dim3(S_LEN / BM, GU_N / BN), 256, GEMM_SMEM>>>(
            p_x, p_wh, p_wl, nullptr, p_gu, GU_N, HID);

        silu_h<<<S_LEN, 256>>>(p_gu, p_x);

        // down-proj + residual
        wq(down_w + l * wsg, p_wh, p_wl, wsg);
        gemm_fp16<true><<<dim3(S_LEN / BM, HID / BN), 256, GEMM_SMEM>>>(
            p_x, p_wh, p_wl, p_a, p_h, HID, INTER);
    }

    rmsnorm_h<<<S_LEN, 256>>>(p_h, final_ln, p_x);
    wq(lm_head_w, p_wh, p_wl, (size_t)VOCAB * HID);
    gemm_fp16<false><<<dim3(S_LEN / BM, VOCAB / BN), 256, GEMM_SMEM>>>(
        p_x, p_wh, p_wl, nullptr, out, VOCAB, HID);
}

// round 6
// speedup vs baseline: 1.9608x; 1.0353x over previous
#include <cuda_runtime.h>
#include <cuda_fp16.h>
#include <stdint.h>
#include <math.h>

// ---------------- problem constants ----------------
#define L_LAYERS 2
#define S_LEN    1024
#define HID      2048
#define NH       16
#define HD       128
#define INTER    5632
#define VOCAB    32000
#define EPS_RMS  1e-5f
#define ATT_SCALE 0.08838834764831845f  // 1/sqrt(128)
#define QKV_N    (3 * HID)    // 6144
#define GU_N     (2 * INTER)  // 11264

// ---------------- GEMM tile config ----------------
#define BM 128
#define BN 128
#define KC 64                      // K elems per stage (fp16 -> 128B rows)
#define NSTAGE 4
#define TILEB 16384                // one 128x64 fp16 tile (128 rows x 128B)
#define STAGE_BYTES (3 * TILEB)    // A, Bh, Bl = 49152
#define GEMM_SMEM (NSTAGE * STAGE_BYTES)   // 196608

// ---------------- scratch (device globals; no allocs allowed) ----------------
__device__ __align__(1024) __half g_wh[(size_t)VOCAB * HID];   // weight hi
__device__ __align__(1024) __half g_wl[(size_t)VOCAB * HID];   // weight lo
__device__ __align__(1024) __half g_x[(size_t)S_LEN * INTER];  // activations fp16
__device__ __align__(1024) __half g_gu[(size_t)S_LEN * GU_N];  // gate|up fp16
__device__ __align__(1024) float  g_h[S_LEN * HID];
__device__ __align__(1024) float  g_a[S_LEN * HID];
__device__ __align__(1024) float  g_qkv[(size_t)S_LEN * QKV_N];

// ---------------- PTX helpers ----------------
typedef unsigned long long u64t;
__device__ __forceinline__ uint32_t smem_u32(const void* p) {
    uint32_t r;
    asm("{ .reg .u64 t; cvta.to.shared.u64 t, %1; cvt.u32.u64 %0, t; }" : "=r"(r) : "l"(p));
    return r;
}
__device__ __forceinline__ void cpa16(uint32_t s, const void* g) {
    asm volatile("cp.async.cg.shared.global [%0], [%1], 16;" :: "r"(s), "l"(g));
}
__device__ __forceinline__ void ldsm4(uint32_t* r, uint32_t addr) {
    asm volatile("ldmatrix.sync.aligned.m8n8.x4.shared.b16 {%0,%1,%2,%3}, [%4];"
                 : "=r"(r[0]), "=r"(r[1]), "=r"(r[2]), "=r"(r[3]) : "r"(addr));
}
__device__ __forceinline__ void mma16816(float* d, const uint32_t* a, uint32_t b0, uint32_t b1) {
    asm volatile("mma.sync.aligned.m16n8k16.row.col.f32.f16.f16.f32 "
                 "{%0,%1,%2,%3}, {%4,%5,%6,%7}, {%8,%9}, {%0,%1,%2,%3};"
                 : "+f"(d[0]), "+f"(d[1]), "+f"(d[2]), "+f"(d[3])
                 : "r"(a[0]), "r"(a[1]), "r"(a[2]), "r"(a[3]), "r"(b0), "r"(b1));
}
// packed f32x2 (sm_100 family)
__device__ __forceinline__ u64t pk2(float x, float y) {
    u64t d; asm("mov.b64 %0, {%1, %2};" : "=l"(d) : "f"(x), "f"(y)); return d;
}
__device__ __forceinline__ void upk2(float& x, float& y, u64t d) {
    asm("mov.b64 {%0, %1}, %2;" : "=f"(x), "=f"(y) : "l"(d));
}
__device__ __forceinline__ void fma2(u64t& d, u64t a, u64t b) {
    asm("fma.rn.f32x2 %0, %1, %2, %0;" : "+l"(d) : "l"(a), "l"(b));
}
__device__ __forceinline__ void mul2(u64t& d, u64t a) {
    asm("mul.rn.f32x2 %0, %0, %1;" : "+l"(d) : "l"(a));
}
// swizzled smem offset within a 128x128B tile: 8 chunks of 16B per row,
// chunk ^= (row & 7) -> conflict-free for cp.async stores and ldmatrix reads.
__device__ __forceinline__ uint32_t swz(uint32_t tilebase, int row, int ch) {
    return tilebase + (uint32_t)row * 128u + (uint32_t)((ch ^ (row & 7)) << 4);
}

// ---------------- fp16 2-pass GEMM via mma.sync ----------------
// C[M,N] = A[M,K] * (Bh+Bl)[N,K]^T (+ Res), fp32 accum, OT output.
template<bool RES, typename OT>
__global__ void __launch_bounds__(256) gemm_fp16(
        const __half* __restrict__ A,
        const __half* __restrict__ Bh, const __half* __restrict__ Bl,
        const float* __restrict__ Res, OT* __restrict__ C,
        int N, int K) {
    extern __shared__ char smem[];
    const uint32_t sb = smem_u32(smem);
    const int tid = threadIdx.x;
    const int lane = tid & 31;
    const int wid = tid >> 5;
    const int warp_m = wid & 1;
    const int warp_n = wid >> 1;
    const int bm = blockIdx.x * BM;
    const int bn = blockIdx.y * BN;
    const int nst = K / KC;
    const size_t rowb = (size_t)K * 2;

    const char* baseA = (const char*)A  + (size_t)bm * rowb;
    const char* baseH = (const char*)Bh + (size_t)bn * rowb;
    const char* baseL = (const char*)Bl + (size_t)bn * rowb;

    const int mat = lane >> 3;
    const int i8r = lane & 7;
    const int mrow_off = ((mat & 1) << 3) + i8r;   // 0..15
    const int ch_off = mat >> 1;                   // 0 or 1

    float acc[4][4][4];
#pragma unroll
    for (int a = 0; a < 4; ++a)
#pragma unroll
        for (int b = 0; b < 4; ++b)
#pragma unroll
            for (int c = 0; c < 4; ++c) acc[a][b][c] = 0.f;

    auto load_stage = [&](int j) {
        const uint32_t stb = sb + (uint32_t)(j & (NSTAGE - 1)) * STAGE_BYTES;
        const size_t koff = (size_t)j * 128;   // KC*2 bytes
#pragma unroll
        for (int p = 0; p < 12; ++p) {
            int lin = p * 256 + tid;           // 0..3071
            int tile = lin >> 10;              // 0:A 1:Bh 2:Bl
            int wt = lin & 1023;
            int row = wt >> 3, ch = wt & 7;
            const char* gb = (tile == 0 ? baseA : (tile == 1 ? baseH : baseL));
            cpa16(swz(stb + (uint32_t)tile * TILEB, row, ch),
                  gb + koff + (size_t)row * rowb + ch * 16);
        }
        asm volatile("cp.async.commit_group;" ::: "memory");
    };

    for (int j = 0; j < 3; ++j) load_stage(j);

    for (int i = 0; i < nst; ++i) {
        int allow = nst - 1 - i; if (allow > 2) allow = 2;
        if (allow == 2)      asm volatile("cp.async.wait_group 2;" ::: "memory");
        else if (allow == 1) asm volatile("cp.async.wait_group 1;" ::: "memory");
        else                 asm volatile("cp.async.wait_group 0;" ::: "memory");
        __syncthreads();
        if (i + 3 < nst) load_stage(i + 3);

        const uint32_t stb = sb + (uint32_t)(i & (NSTAGE - 1)) * STAGE_BYTES;
#pragma unroll
        for (int h = 0; h < 4; ++h) {          // 4 x k16 within KC=64
            uint32_t af[4][4], bh[2][4], bl[2][4];
#pragma unroll
            for (int mt = 0; mt < 4; ++mt) {
                int r = warp_m * 64 + mt * 16 + mrow_off;
                ldsm4(af[mt], swz(stb, r, h * 2 + ch_off));
            }
#pragma unroll
            for (int nb = 0; nb < 2; ++nb) {
                int r = warp_n * 32 + nb * 16 + mrow_off;
                ldsm4(bh[nb], swz(stb + TILEB,     r, h * 2 + ch_off));
                ldsm4(bl[nb], swz(stb + 2 * TILEB, r, h * 2 + ch_off));
            }
#pragma unroll
            for (int mt = 0; mt < 4; ++mt)
#pragma unroll
                for (int nt = 0; nt < 4; ++nt) {
                    int np = nt >> 1, sub = nt & 1;
                    float* d = acc[mt][nt];
                    mma16816(d, af[mt], bh[np][sub], bh[np][sub + 2]);  // A*Bh
                    mma16816(d, af[mt], bl[np][sub], bl[np][sub + 2]);  // A*Bl
                }
        }
    }

    // epilogue
#pragma unroll
    for (int mt = 0; mt < 4; ++mt)
#pragma unroll
        for (int nt = 0; nt < 4; ++nt) {
            int row = bm + warp_m * 64 + mt * 16 + (lane >> 2);
            int col = bn + warp_n * 32 + nt * 8 + ((lane & 3) << 1);
            float* d = acc[mt][nt];
            size_t o0 = (size_t)row * N + col;
            size_t o1 = (size_t)(row + 8) * N + col;
            if (RES) {
                d[0] += Res[o0]; d[1] += Res[o0 + 1];
                d[2] += Res[o1]; d[3] += Res[o1 + 1];
            }
            if (sizeof(OT) == 4) {
                *(float2*)((float*)C + o0) = make_float2(d[0], d[1]);
                *(float2*)((float*)C + o1) = make_float2(d[2], d[3]);
            } else {
                *(__half2*)((__half*)C + o0) =
                    __halves2half2(__float2half(d[0]), __float2half(d[1]));
                *(__half2*)((__half*)C + o1) =
                    __halves2half2(__float2half(d[2]), __float2half(d[3]));
            }
        }
}

// ---------------- weight quant: exact int4 sim -> fp16 hi/lo ----------------
// 4 threads per group of 32 along K; 2x float4 loads, uint4 stores.
__global__ void wquant_h(const float* __restrict__ w, __half* __restrict__ oh,
                         __half* __restrict__ ol, int ngroups) {
    int t = blockIdx.x * blockDim.x + threadIdx.x;
    int gid = t >> 2, l4 = t & 3;
    if (gid >= ngroups) return;
    size_t base = (size_t)gid * 32 + l4 * 8;
    float4 a4 = *(const float4*)(w + base);
    float4 b4 = *(const float4*)(w + base + 4);
    float vv[8] = { a4.x, a4.y, a4.z, a4.w, b4.x, b4.y, b4.z, b4.w };
    float a = 0.f;
#pragma unroll
    for (int c = 0; c < 8; ++c) a = fmaxf(a, fabsf(vv[c]));
    a = fmaxf(a, __shfl_xor_sync(0xffffffffu, a, 1));
    a = fmaxf(a, __shfl_xor_sync(0xffffffffu, a, 2));
    float s = a / 7.0f + 1e-12f;
    __half hb[8], lb[8];
#pragma unroll
    for (int c = 0; c < 8; ++c) {
        float v = fminf(fmaxf(rintf(vv[c] / s), -8.f), 7.f) * s;
        hb[c] = __float2half(v);
        lb[c] = __float2half(v - __half2float(hb[c]));
    }
    *(uint4*)(oh + base) = *(uint4*)hb;
    *(uint4*)(ol + base) = *(uint4*)lb;
}

// ---------------- embedding gather ----------------
__global__ void embed_kernel(const int* __restrict__ ids, const float* __restrict__ ew,
                             float* __restrict__ h) {
    int s = blockIdx.x;
    int tok = ids[s];
    const float4* src = (const float4*)(ew + (size_t)tok * HID);
    float4* dst = (float4*)(h + (size_t)s * HID);
    for (int i = threadIdx.x; i < HID / 4; i += blockDim.x) dst[i] = src[i];
}

// ---------------- rmsnorm -> fp16 ----------------
__global__ void rmsnorm_h(const float* __restrict__ x, const float* __restrict__ w,
                          __half* __restrict__ o) {
    int row = blockIdx.x;
    const float* xr = x + (size_t)row * HID;
    float s = 0.f;
    for (int i = threadIdx.x; i < HID; i += 256) { float v = xr[i]; s += v * v; }
#pragma unroll
    for (int off = 16; off; off >>= 1) s += __shfl_xor_sync(0xffffffffu, s, off);
    __shared__ float red[8];
    __shared__ float rtot;
    if ((threadIdx.x & 31) == 0) red[threadIdx.x >> 5] = s;
    __syncthreads();
    if (threadIdx.x == 0) {
        float t = 0.f;
#pragma unroll
        for (int i = 0; i < 8; ++i) t += red[i];
        rtot = rsqrtf(t / (float)HID + EPS_RMS);
    }
    __syncthreads();
    float r = rtot;
    size_t base = (size_t)row * HID;
    for (int i = threadIdx.x; i < HID; i += 256)
        o[base + i] = __float2half(xr[i] * r * w[i]);
}

// ---------------- rope (llama half-split), in-place on fused qkv ----------------
__global__ void rope_kernel(float* __restrict__ qkv, const int* __restrict__ pos_ptr) {
    int s = blockIdx.x, h = blockIdx.y, d = threadIdx.x;  // d in [0,64)
    int pos = pos_ptr[0] + s;
    float invf = (float)exp(-((double)(2 * d) / 128.0) * log(10000.0));
    float ang  = (float)pos * invf;
    float cs = (float)cos((double)ang);
    float sn = (float)sin((double)ang);
    size_t base = (size_t)s * QKV_N + h * HD;
    float x1 = qkv[base + d], x2 = qkv[base + d + 64];
    qkv[base + d]      = x1 * cs - x2 * sn;
    qkv[base + d + 64] = x2 * cs + x1 * sn;
    size_t kb = base + HID;
    x1 = qkv[kb + d]; x2 = qkv[kb + d + 64];
    qkv[kb + d]      = x1 * cs - x2 * sn;
    qkv[kb + d + 64] = x2 * cs + x1 * sn;
}

// ---------------- flash attention, fp32 via f32x2, 64q x 32k tiles; out fp16 ----------------
__global__ void __launch_bounds__(256) attn_kernel(const float* __restrict__ qkv,
                                                   __half* __restrict__ ctx,
                                                   const int* __restrict__ pos_ptr) {
    __shared__ float Ks[32 * 130];
    __shared__ float Vs[32 * 130];
    __shared__ float Ps[64 * 33];
    const int h = blockIdx.x;
    const int qt = blockIdx.y;
    const int tid = threadIdx.x;
    const int r = tid >> 2;
    const int c = tid & 3;
    const int pid = pos_ptr[0];
    const int s = qt * 64 + r;
    const int pos = pid + s;

    u64t q2[16], o2[16];
    const float* qp = qkv + (size_t)s * QKV_N + h * HD + c * 32;
#pragma unroll
    for (int t = 0; t < 16; ++t) {
        int idx = (2 * t + 8 * c) & 31;
        float2 v = *(const float2*)(qp + idx);
        q2[t] = pk2(v.x, v.y);
        o2[t] = 0ull;
    }
    float m = -1e30f, l = 0.f;

    int maxpos = pid + qt * 64 + 63;
    int ntiles = maxpos / 32 + 1;
    if (ntiles > S_LEN / 32) ntiles = S_LEN / 32;

    for (int jt = 0; jt < ntiles; ++jt) {
        __syncthreads();
        for (int idx = tid; idx < 32 * 128; idx += 256) {
            int row = idx >> 7, col = idx & 127;
            size_t g = (size_t)(jt * 32 + row) * QKV_N + h * HD + col;
            Ks[row * 130 + col] = qkv[g + HID];
            Vs[row * 130 + col] = qkv[g + 2 * HID];
        }
        __syncthreads();

        float tmax = -1e30f;
        for (int j = 0; j < 32; ++j) {
            const float* kr = &Ks[j * 130 + c * 32];
            u64t p2 = 0ull;
#pragma unroll
            for (int t = 0; t < 16; ++t) {
                int idx = (2 * t + 8 * c) & 31;
                float2 v = *(const float2*)(kr + idx);
                fma2(p2, q2[t], pk2(v.x, v.y));
            }
            float px, py; upk2(px, py, p2);
            float p = px + py;
            p += __shfl_xor_sync(0xffffffffu, p, 1);
            p += __shfl_xor_sync(0xffffffffu, p, 2);
            float val = ((jt * 32 + j) <= pos) ? p * ATT_SCALE : -1e30f;
            tmax = fmaxf(tmax, val);
            if ((j & 3) == c) Ps[r * 33 + j] = val;
        }
        __syncwarp();
        float mnew = fmaxf(m, tmax);
        float sf = expf(m - mnew);
        float tsum = 0.f;
#pragma unroll
        for (int jj = 0; jj < 8; ++jj) {
            int j = jj * 4 + c;
            float e = expf(Ps[r * 33 + j] - mnew);
            Ps[r * 33 + j] = e;
            tsum += e;
        }
        tsum += __shfl_xor_sync(0xffffffffu, tsum, 1);
        tsum += __shfl_xor_sync(0xffffffffu, tsum, 2);
        __syncwarp();
        l = l * sf + tsum;
        m = mnew;
        u64t sf2 = pk2(sf, sf);
#pragma unroll
        for (int t = 0; t < 16; ++t) mul2(o2[t], sf2);
        for (int j = 0; j < 32; ++j) {
            float pv = Ps[r * 33 + j];
            u64t pv2 = pk2(pv, pv);
            const float* vr = &Vs[j * 130 + c * 32];
#pragma unroll
            for (int t = 0; t < 16; ++t) {
                int idx = (2 * t + 8 * c) & 31;
                float2 v = *(const float2*)(vr + idx);
                fma2(o2[t], pv2, pk2(v.x, v.y));
            }
        }
    }
    float inv = 1.f / l;
    size_t cbase = (size_t)s * HID + h * HD + c * 32;
#pragma unroll
    for (int t = 0; t < 16; ++t) {
        int idx = (2 * t + 8 * c) & 31;
        float x, y; upk2(x, y, o2[t]);
        *(__half2*)(ctx + cbase + idx) =
            __halves2half2(__float2half(x * inv), __float2half(y * inv));
    }
}

// ---------------- SwiGLU: u = up * gate * sigmoid(gate) -> fp16 ----------------
__global__ void silu_h(const __half* __restrict__ gu, __half* __restrict__ o) {
    int s = blockIdx.x;
    const __half* row = gu + (size_t)s * GU_N;
    size_t ob = (size_t)s * INTER;
    for (int j = threadIdx.x; j < INTER; j += 256) {
        float g = __half2float(row[j]);
        float u = __half2float(row[INTER + j]);
        o[ob + j] = __float2half(u * g / (1.f + expf(-g)));
    }
}

// ---------------- host orchestration ----------------
static void wq(const float* w, __half* dh, __half* dl, size_t nelem) {
    int ngroups = (int)(nelem / 32);
    int threads = ngroups * 4;
    wquant_h<<<(threads + 255) / 256, 256>>>(w, dh, dl, ngroups);
}

extern "C" void kernel_launch(void* const* d_in, const int* in_sizes, int n_in,
                              void* d_out, int out_size) {
    const int*   input_ids = (const int*)d_in[0];
    const int*   pos_id    = (const int*)d_in[3];
    const float* embed_w   = (const float*)d_in[4];
    const float* in_ln_w   = (const float*)d_in[5];
    const float* post_ln_w = (const float*)d_in[6];
    const float* final_ln  = (const float*)d_in[7];
    const float* q_w       = (const float*)d_in[8];
    const float* k_w       = (const float*)d_in[9];
    const float* v_w       = (const float*)d_in[10];
    const float* o_w       = (const float*)d_in[11];
    const float* gate_w    = (const float*)d_in[12];
    const float* up_w      = (const float*)d_in[13];
    const float* down_w    = (const float*)d_in[14];
    const float* lm_head_w = (const float*)d_in[15];
    float* out = (float*)d_out;

    __half *p_wh, *p_wl, *p_x, *p_gu;
    float *p_h, *p_a, *p_qkv;
    cudaGetSymbolAddress((void**)&p_wh, g_wh);
    cudaGetSymbolAddress((void**)&p_wl, g_wl);
    cudaGetSymbolAddress((void**)&p_x, g_x);
    cudaGetSymbolAddress((void**)&p_gu, g_gu);
    cudaGetSymbolAddress((void**)&p_h, g_h);
    cudaGetSymbolAddress((void**)&p_a, g_a);
    cudaGetSymbolAddress((void**)&p_qkv, g_qkv);

    cudaFuncSetAttribute((void*)gemm_fp16<false, float>,
                         cudaFuncAttributeMaxDynamicSharedMemorySize, GEMM_SMEM);
    cudaFuncSetAttribute((void*)gemm_fp16<true, float>,
                         cudaFuncAttributeMaxDynamicSharedMemorySize, GEMM_SMEM);
    cudaFuncSetAttribute((void*)gemm_fp16<false, __half>,
                         cudaFuncAttributeMaxDynamicSharedMemorySize, GEMM_SMEM);

    const size_t wsq = (size_t)HID * HID;
    const size_t wsg = (size_t)INTER * HID;

    embed_kernel<<<S_LEN, 256>>>(input_ids, embed_w, p_h);

    for (int l = 0; l < L_LAYERS; ++l) {
        rmsnorm_h<<<S_LEN, 256>>>(p_h, in_ln_w + l * HID, p_x);

        // fused QKV: dequant q|k|v contiguously, one N=6144 GEMM
        wq(q_w + l * wsq, p_wh,           p_wl,           wsq);
        wq(k_w + l * wsq, p_wh + wsq,     p_wl + wsq,     wsq);
        wq(v_w + l * wsq, p_wh + 2 * wsq, p_wl + 2 * wsq, wsq);
        gemm_fp16<false, float><<<dim3(S_LEN / BM, QKV_N / BN), 256, GEMM_SMEM>>>(
            p_x, p_wh, p_wl, nullptr, p_qkv, QKV_N, HID);

        rope_kernel<<<dim3(S_LEN, NH), 64>>>(p_qkv, pos_id);
        attn_kernel<<<dim3(NH, S_LEN / 64), 256>>>(p_qkv, p_x, pos_id);

        // O-proj + residual
        wq(o_w + l * wsq, p_wh, p_wl, wsq);
        gemm_fp16<true, float><<<dim3(S_LEN / BM, HID / BN), 256, GEMM_SMEM>>>(
            p_x, p_wh, p_wl, p_h, p_a, HID, HID);

        rmsnorm_h<<<S_LEN, 256>>>(p_a, post_ln_w + l * HID, p_x);

        // fused gate|up: one N=11264 GEMM, fp16 output
        wq(gate_w + l * wsg, p_wh,       p_wl,       wsg);
        wq(up_w   + l * wsg, p_wh + wsg, p_wl + wsg, wsg);
        gemm_fp16<false, __half><<<dim3(S_LEN / BM, GU_N / BN), 256, GEMM_SMEM>>>(
            p_x, p_wh, p_wl, nullptr, p_gu, GU_N, HID);

        silu_h<<<S_LEN, 256>>>(p_gu, p_x);

        // down-proj + residual
        wq(down_w + l * wsg, p_wh, p_wl, wsg);
        gemm_fp16<true, float><<<dim3(S_LEN / BM, HID / BN), 256, GEMM_SMEM>>>(
            p_x, p_wh, p_wl, p_a, p_h, HID, INTER);
    }

    rmsnorm_h<<<S_LEN, 256>>>(p_h, final_ln, p_x);
    wq(lm_head_w, p_wh, p_wl, (size_t)VOCAB * HID);
    gemm_fp16<false, float><<<dim3(S_LEN / BM, VOCAB / BN), 256, GEMM_SMEM>>>(
        p_x, p_wh, p_wl, nullptr, out, VOCAB, HID);
}

// round 8
// speedup vs baseline: 2.1454x; 1.0941x over previous
#include <cuda_runtime.h>
#include <cuda_fp16.h>
#include <stdint.h>
#include <math.h>

// ---------------- problem constants ----------------
#define L_LAYERS 2
#define S_LEN    1024
#define HID      2048
#define NH       16
#define HD       128
#define INTER    5632
#define VOCAB    32000
#define EPS_RMS  1e-5f
#define ATT_SCALE 0.08838834764831845f  // 1/sqrt(128)
#define QKV_N    (3 * HID)    // 6144
#define GU_N     (2 * INTER)  // 11264

// ---------------- GEMM tile config ----------------
#define BM 128
#define BN 128
#define KC 64                      // K elems per stage (fp16 -> 128B rows)
#define NSTAGE 4
#define TILEB 16384                // one 128x64 fp16 tile (128 rows x 128B)
#define STAGE_BYTES (3 * TILEB)    // A, Bh, Bl = 49152
#define GEMM_SMEM (NSTAGE * STAGE_BYTES)   // 196608

// epilogue modes
#define MODE_F32   0
#define MODE_RES   1
#define MODE_SWI   2

// ---------------- scratch (device globals; no allocs allowed) ----------------
__device__ __align__(1024) __half g_wh[(size_t)VOCAB * HID];   // weight hi
__device__ __align__(1024) __half g_wl[(size_t)VOCAB * HID];   // weight lo
__device__ __align__(1024) __half g_x[(size_t)S_LEN * HID];    // activations fp16 (GEMM input)
__device__ __align__(1024) __half g_x2[(size_t)S_LEN * INTER]; // MLP activations fp16
__device__ __align__(1024) float  g_h[S_LEN * HID];
__device__ __align__(1024) float  g_a[S_LEN * HID];
__device__ __align__(1024) float  g_qkv[(size_t)S_LEN * QKV_N];

// ---------------- PTX helpers ----------------
typedef unsigned long long u64t;
__device__ __forceinline__ uint32_t smem_u32(const void* p) {
    uint32_t r;
    asm("{ .reg .u64 t; cvta.to.shared.u64 t, %1; cvt.u32.u64 %0, t; }" : "=r"(r) : "l"(p));
    return r;
}
__device__ __forceinline__ void cpa16(uint32_t s, const void* g) {
    asm volatile("cp.async.cg.shared.global [%0], [%1], 16;" :: "r"(s), "l"(g));
}
__device__ __forceinline__ void ldsm4(uint32_t* r, uint32_t addr) {
    asm volatile("ldmatrix.sync.aligned.m8n8.x4.shared.b16 {%0,%1,%2,%3}, [%4];"
                 : "=r"(r[0]), "=r"(r[1]), "=r"(r[2]), "=r"(r[3]) : "r"(addr));
}
__device__ __forceinline__ void mma16816(float* d, const uint32_t* a, uint32_t b0, uint32_t b1) {
    asm volatile("mma.sync.aligned.m16n8k16.row.col.f32.f16.f16.f32 "
                 "{%0,%1,%2,%3}, {%4,%5,%6,%7}, {%8,%9}, {%0,%1,%2,%3};"
                 : "+f"(d[0]), "+f"(d[1]), "+f"(d[2]), "+f"(d[3])
                 : "r"(a[0]), "r"(a[1]), "r"(a[2]), "r"(a[3]), "r"(b0), "r"(b1));
}
// packed f32x2 (sm_100 family)
__device__ __forceinline__ u64t pk2(float x, float y) {
    u64t d; asm("mov.b64 %0, {%1, %2};" : "=l"(d) : "f"(x), "f"(y)); return d;
}
__device__ __forceinline__ void upk2(float& x, float& y, u64t d) {
    asm("mov.b64 {%0, %1}, %2;" : "=f"(x), "=f"(y) : "l"(d));
}
__device__ __forceinline__ void fma2(u64t& d, u64t a, u64t b) {
    asm("fma.rn.f32x2 %0, %1, %2, %0;" : "+l"(d) : "l"(a), "l"(b));
}
__device__ __forceinline__ void mul2(u64t& d, u64t a) {
    asm("mul.rn.f32x2 %0, %0, %1;" : "+l"(d) : "l"(a));
}
// swizzled smem offset within a 128x128B tile: 8 chunks of 16B per row,
// chunk ^= (row & 7) -> conflict-free for cp.async stores and ldmatrix reads.
__device__ __forceinline__ uint32_t swz(uint32_t tilebase, int row, int ch) {
    return tilebase + (uint32_t)row * 128u + (uint32_t)((ch ^ (row & 7)) << 4);
}

// ---------------- fp16 2-pass GEMM via mma.sync ----------------
// C[M,N] = A[M,K] * (Bh+Bl)[N,K]^T, fp32 accum.
// MODE_F32: fp32 out.  MODE_RES: fp32 out + residual.
// MODE_SWI: gate/up interleaved cols -> u*g*sigmoid(g) -> fp16 out [M, N/2].
template<int MODE>
__global__ void __launch_bounds__(256) gemm_fp16(
        const __half* __restrict__ A,
        const __half* __restrict__ Bh, const __half* __restrict__ Bl,
        const float* __restrict__ Res, void* __restrict__ Cv,
        int N, int K) {
    extern __shared__ char smem[];
    const uint32_t sb = smem_u32(smem);
    const int tid = threadIdx.x;
    const int lane = tid & 31;
    const int wid = tid >> 5;
    const int warp_m = wid & 1;
    const int warp_n = wid >> 1;
    const int bm = blockIdx.x * BM;
    const int bn = blockIdx.y * BN;
    const int nst = K / KC;
    const size_t rowb = (size_t)K * 2;

    const char* baseA = (const char*)A  + (size_t)bm * rowb;
    const char* baseH = (const char*)Bh + (size_t)bn * rowb;
    const char* baseL = (const char*)Bl + (size_t)bn * rowb;

    const int mat = lane >> 3;
    const int i8r = lane & 7;
    const int mrow_off = ((mat & 1) << 3) + i8r;   // 0..15
    const int ch_off = mat >> 1;                   // 0 or 1

    float acc[4][4][4];
#pragma unroll
    for (int a = 0; a < 4; ++a)
#pragma unroll
        for (int b = 0; b < 4; ++b)
#pragma unroll
            for (int c = 0; c < 4; ++c) acc[a][b][c] = 0.f;

    auto load_stage = [&](int j) {
        const uint32_t stb = sb + (uint32_t)(j & (NSTAGE - 1)) * STAGE_BYTES;
        const size_t koff = (size_t)j * 128;   // KC*2 bytes
#pragma unroll
        for (int p = 0; p < 12; ++p) {
            int lin = p * 256 + tid;           // 0..3071
            int tile = lin >> 10;              // 0:A 1:Bh 2:Bl
            int wt = lin & 1023;
            int row = wt >> 3, ch = wt & 7;
            const char* gb = (tile == 0 ? baseA : (tile == 1 ? baseH : baseL));
            cpa16(swz(stb + (uint32_t)tile * TILEB, row, ch),
                  gb + koff + (size_t)row * rowb + ch * 16);
        }
        asm volatile("cp.async.commit_group;" ::: "memory");
    };

    for (int j = 0; j < 3; ++j) load_stage(j);

    for (int i = 0; i < nst; ++i) {
        int allow = nst - 1 - i; if (allow > 2) allow = 2;
        if (allow == 2)      asm volatile("cp.async.wait_group 2;" ::: "memory");
        else if (allow == 1) asm volatile("cp.async.wait_group 1;" ::: "memory");
        else                 asm volatile("cp.async.wait_group 0;" ::: "memory");
        __syncthreads();
        if (i + 3 < nst) load_stage(i + 3);

        const uint32_t stb = sb + (uint32_t)(i & (NSTAGE - 1)) * STAGE_BYTES;
#pragma unroll
        for (int h = 0; h < 4; ++h) {          // 4 x k16 within KC=64
            uint32_t af[4][4], bh[2][4], bl[2][4];
#pragma unroll
            for (int mt = 0; mt < 4; ++mt) {
                int r = warp_m * 64 + mt * 16 + mrow_off;
                ldsm4(af[mt], swz(stb, r, h * 2 + ch_off));
            }
#pragma unroll
            for (int nb = 0; nb < 2; ++nb) {
                int r = warp_n * 32 + nb * 16 + mrow_off;
                ldsm4(bh[nb], swz(stb + TILEB,     r, h * 2 + ch_off));
                ldsm4(bl[nb], swz(stb + 2 * TILEB, r, h * 2 + ch_off));
            }
#pragma unroll
            for (int mt = 0; mt < 4; ++mt)
#pragma unroll
                for (int nt = 0; nt < 4; ++nt) {
                    int np = nt >> 1, sub = nt & 1;
                    float* d = acc[mt][nt];
                    mma16816(d, af[mt], bh[np][sub], bh[np][sub + 2]);  // A*Bh
                    mma16816(d, af[mt], bl[np][sub], bl[np][sub + 2]);  // A*Bl
                }
        }
    }

    // epilogue
#pragma unroll
    for (int mt = 0; mt < 4; ++mt)
#pragma unroll
        for (int nt = 0; nt < 4; ++nt) {
            int row = bm + warp_m * 64 + mt * 16 + (lane >> 2);
            int col = bn + warp_n * 32 + nt * 8 + ((lane & 3) << 1);
            float* d = acc[mt][nt];
            if (MODE == MODE_SWI) {
                // col is even: (gate, up) interleaved. out[M, N/2] fp16.
                __half* X = (__half*)Cv;
                int colh = col >> 1;
                float g0 = d[0], u0 = d[1];
                X[(size_t)row * (N / 2) + colh] =
                    __float2half(u0 * g0 / (1.f + __expf(-g0)));
                float g1 = d[2], u1 = d[3];
                X[(size_t)(row + 8) * (N / 2) + colh] =
                    __float2half(u1 * g1 / (1.f + __expf(-g1)));
            } else {
                float* C = (float*)Cv;
                size_t o0 = (size_t)row * N + col;
                size_t o1 = (size_t)(row + 8) * N + col;
                if (MODE == MODE_RES) {
                    d[0] += Res[o0]; d[1] += Res[o0 + 1];
                    d[2] += Res[o1]; d[3] += Res[o1 + 1];
                }
                *(float2*)(C + o0) = make_float2(d[0], d[1]);
                *(float2*)(C + o1) = make_float2(d[2], d[3]);
            }
        }
}

// ---------------- weight quant: exact int4 sim -> fp16 hi/lo ----------------
// 4 threads per group of 32 along K; 2x float4 loads, uint4 stores.
// dst row remap: source row n -> dst row (rowmul*n + rowoff)  (gate/up interleave)
__global__ void wquant_h(const float* __restrict__ w, __half* __restrict__ oh,
                         __half* __restrict__ ol, int ngroups, int gpk,
                         int rowmul, int rowoff, int K) {
    int t = blockIdx.x * blockDim.x + threadIdx.x;
    int gid = t >> 2, l4 = t & 3;
    if (gid >= ngroups) return;
    size_t sbase = (size_t)gid * 32 + l4 * 8;
    int n = gid / gpk, g = gid - n * gpk;
    size_t dbase = (size_t)(rowmul * n + rowoff) * K + g * 32 + l4 * 8;
    float4 a4 = *(const float4*)(w + sbase);
    float4 b4 = *(const float4*)(w + sbase + 4);
    float vv[8] = { a4.x, a4.y, a4.z, a4.w, b4.x, b4.y, b4.z, b4.w };
    float a = 0.f;
#pragma unroll
    for (int c = 0; c < 8; ++c) a = fmaxf(a, fabsf(vv[c]));
    a = fmaxf(a, __shfl_xor_sync(0xffffffffu, a, 1));
    a = fmaxf(a, __shfl_xor_sync(0xffffffffu, a, 2));
    float s = a / 7.0f + 1e-12f;
    __half hb[8], lb[8];
#pragma unroll
    for (int c = 0; c < 8; ++c) {
        float v = fminf(fmaxf(rintf(vv[c] / s), -8.f), 7.f) * s;
        hb[c] = __float2half(v);
        lb[c] = __float2half(v - __half2float(hb[c]));
    }
    *(uint4*)(oh + dbase) = *(uint4*)hb;
    *(uint4*)(ol + dbase) = *(uint4*)lb;
}

// ---------------- embedding gather ----------------
__global__ void embed_kernel(const int* __restrict__ ids, const float* __restrict__ ew,
                             float* __restrict__ h) {
    int s = blockIdx.x;
    int tok = ids[s];
    const float4* src = (const float4*)(ew + (size_t)tok * HID);
    float4* dst = (float4*)(h + (size_t)s * HID);
    for (int i = threadIdx.x; i < HID / 4; i += blockDim.x) dst[i] = src[i];
}

// ---------------- rmsnorm -> fp16 ----------------
__global__ void rmsnorm_h(const float* __restrict__ x, const float* __restrict__ w,
                          __half* __restrict__ o) {
    int row = blockIdx.x;
    const float* xr = x + (size_t)row * HID;
    float s = 0.f;
    for (int i = threadIdx.x; i < HID; i += 256) { float v = xr[i]; s += v * v; }
#pragma unroll
    for (int off = 16; off; off >>= 1) s += __shfl_xor_sync(0xffffffffu, s, off);
    __shared__ float red[8];
    __shared__ float rtot;
    if ((threadIdx.x & 31) == 0) red[threadIdx.x >> 5] = s;
    __syncthreads();
    if (threadIdx.x == 0) {
        float t = 0.f;
#pragma unroll
        for (int i = 0; i < 8; ++i) t += red[i];
        rtot = rsqrtf(t / (float)HID + EPS_RMS);
    }
    __syncthreads();
    float r = rtot;
    size_t base = (size_t)row * HID;
    for (int i = threadIdx.x; i < HID; i += 256)
        o[base + i] = __float2half(xr[i] * r * w[i]);
}

// ---------------- rope (llama half-split), fp32, in-place on fused qkv ----------------
__global__ void rope_kernel(float* __restrict__ qkv, const int* __restrict__ pos_ptr) {
    int s = blockIdx.x, h = blockIdx.y, d = threadIdx.x;  // d in [0,64)
    int pos = pos_ptr[0] + s;
    // matches reference fp32 semantics: inv_freq = 10000^(-d/64) in fp32
    float invf = powf(10000.f, -(float)d * (1.f / 64.f));
    float ang  = (float)pos * invf;
    float cs = cosf(ang);
    float sn = sinf(ang);
    size_t base = (size_t)s * QKV_N + h * HD;
    float x1 = qkv[base + d], x2 = qkv[base + d + 64];
    qkv[base + d]      = x1 * cs - x2 * sn;
    qkv[base + d + 64] = x2 * cs + x1 * sn;
    size_t kb = base + HID;
    x1 = qkv[kb + d]; x2 = qkv[kb + d + 64];
    qkv[kb + d]      = x1 * cs - x2 * sn;
    qkv[kb + d + 64] = x2 * cs + x1 * sn;
}

// ---------------- flash attention, fp32 via f32x2, 64q x 32k tiles; out fp16 ----------------
__global__ void __launch_bounds__(256) attn_kernel(const float* __restrict__ qkv,
                                                   __half* __restrict__ ctx,
                                                   const int* __restrict__ pos_ptr) {
    __shared__ float Ks[32 * 130];
    __shared__ float Vs[32 * 130];
    __shared__ float Ps[64 * 33];
    const int h = blockIdx.x;
    const int qt = blockIdx.y;
    const int tid = threadIdx.x;
    const int r = tid >> 2;
    const int c = tid & 3;
    const int pid = pos_ptr[0];
    const int s = qt * 64 + r;
    const int pos = pid + s;

    u64t q2[16], o2[16];
    const float* qp = qkv + (size_t)s * QKV_N + h * HD + c * 32;
#pragma unroll
    for (int t = 0; t < 16; ++t) {
        int idx = (2 * t + 8 * c) & 31;
        float2 v = *(const float2*)(qp + idx);
        q2[t] = pk2(v.x, v.y);
        o2[t] = 0ull;
    }
    float m = -1e30f, l = 0.f;

    int maxpos = pid + qt * 64 + 63;
    int ntiles = maxpos / 32 + 1;
    if (ntiles > S_LEN / 32) ntiles = S_LEN / 32;

    for (int jt = 0; jt < ntiles; ++jt) {
        __syncthreads();
        for (int idx = tid; idx < 32 * 128; idx += 256) {
            int row = idx >> 7, col = idx & 127;
            size_t g = (size_t)(jt * 32 + row) * QKV_N + h * HD + col;
            Ks[row * 130 + col] = qkv[g + HID];
            Vs[row * 130 + col] = qkv[g + 2 * HID];
        }
        __syncthreads();

        float tmax = -1e30f;
        for (int j = 0; j < 32; ++j) {
            const float* kr = &Ks[j * 130 + c * 32];
            u64t p2 = 0ull;
#pragma unroll
            for (int t = 0; t < 16; ++t) {
                int idx = (2 * t + 8 * c) & 31;
                float2 v = *(const float2*)(kr + idx);
                fma2(p2, q2[t], pk2(v.x, v.y));
            }
            float px, py; upk2(px, py, p2);
            float p = px + py;
            p += __shfl_xor_sync(0xffffffffu, p, 1);
            p += __shfl_xor_sync(0xffffffffu, p, 2);
            float val = ((jt * 32 + j) <= pos) ? p * ATT_SCALE : -1e30f;
            tmax = fmaxf(tmax, val);
            if ((j & 3) == c) Ps[r * 33 + j] = val;
        }
        __syncwarp();
        float mnew = fmaxf(m, tmax);
        float sf = __expf(m - mnew);
        float tsum = 0.f;
#pragma unroll
        for (int jj = 0; jj < 8; ++jj) {
            int j = jj * 4 + c;
            float e = __expf(Ps[r * 33 + j] - mnew);
            Ps[r * 33 + j] = e;
            tsum += e;
        }
        tsum += __shfl_xor_sync(0xffffffffu, tsum, 1);
        tsum += __shfl_xor_sync(0xffffffffu, tsum, 2);
        __syncwarp();
        l = l * sf + tsum;
        m = mnew;
        u64t sf2 = pk2(sf, sf);
#pragma unroll
        for (int t = 0; t < 16; ++t) mul2(o2[t], sf2);
        for (int j = 0; j < 32; ++j) {
            float pv = Ps[r * 33 + j];
            u64t pv2 = pk2(pv, pv);
            const float* vr = &Vs[j * 130 + c * 32];
#pragma unroll
            for (int t = 0; t < 16; ++t) {
                int idx = (2 * t + 8 * c) & 31;
                float2 v = *(const float2*)(vr + idx);
                fma2(o2[t], pv2, pk2(v.x, v.y));
            }
        }
    }
    float inv = 1.f / l;
    size_t cbase = (size_t)s * HID + h * HD + c * 32;
#pragma unroll
    for (int t = 0; t < 16; ++t) {
        int idx = (2 * t + 8 * c) & 31;
        float x, y; upk2(x, y, o2[t]);
        *(__half2*)(ctx + cbase + idx) =
            __halves2half2(__float2half(x * inv), __float2half(y * inv));
    }
}

// ---------------- host orchestration ----------------
static void wq(const float* w, __half* dh, __half* dl, size_t nelem, int K,
               int rowmul = 1, int rowoff = 0) {
    int ngroups = (int)(nelem / 32);
    int gpk = K / 32;
    int threads = ngroups * 4;
    wquant_h<<<(threads + 255) / 256, 256>>>(w, dh, dl, ngroups, gpk, rowmul, rowoff, K);
}

extern "C" void kernel_launch(void* const* d_in, const int* in_sizes, int n_in,
                              void* d_out, int out_size) {
    const int*   input_ids = (const int*)d_in[0];
    const int*   pos_id    = (const int*)d_in[3];
    const float* embed_w   = (const float*)d_in[4];
    const float* in_ln_w   = (const float*)d_in[5];
    const float* post_ln_w = (const float*)d_in[6];
    const float* final_ln  = (const float*)d_in[7];
    const float* q_w       = (const float*)d_in[8];
    const float* k_w       = (const float*)d_in[9];
    const float* v_w       = (const float*)d_in[10];
    const float* o_w       = (const float*)d_in[11];
    const float* gate_w    = (const float*)d_in[12];
    const float* up_w      = (const float*)d_in[13];
    const float* down_w    = (const float*)d_in[14];
    const float* lm_head_w = (const float*)d_in[15];
    float* out = (float*)d_out;

    __half *p_wh, *p_wl, *p_x, *p_x2;
    float *p_h, *p_a, *p_qkv;
    cudaGetSymbolAddress((void**)&p_wh, g_wh);
    cudaGetSymbolAddress((void**)&p_wl, g_wl);
    cudaGetSymbolAddress((void**)&p_x, g_x);
    cudaGetSymbolAddress((void**)&p_x2, g_x2);
    cudaGetSymbolAddress((void**)&p_h, g_h);
    cudaGetSymbolAddress((void**)&p_a, g_a);
    cudaGetSymbolAddress((void**)&p_qkv, g_qkv);

    cudaFuncSetAttribute((void*)gemm_fp16<MODE_F32>,
                         cudaFuncAttributeMaxDynamicSharedMemorySize, GEMM_SMEM);
    cudaFuncSetAttribute((void*)gemm_fp16<MODE_RES>,
                         cudaFuncAttributeMaxDynamicSharedMemorySize, GEMM_SMEM);
    cudaFuncSetAttribute((void*)gemm_fp16<MODE_SWI>,
                         cudaFuncAttributeMaxDynamicSharedMemorySize, GEMM_SMEM);

    const size_t wsq = (size_t)HID * HID;
    const size_t wsg = (size_t)INTER * HID;

    embed_kernel<<<S_LEN, 256>>>(input_ids, embed_w, p_h);

    for (int l = 0; l < L_LAYERS; ++l) {
        rmsnorm_h<<<S_LEN, 256>>>(p_h, in_ln_w + l * HID, p_x);

        // fused QKV: dequant q|k|v contiguously, one N=6144 GEMM
        wq(q_w + l * wsq, p_wh,           p_wl,           wsq, HID);
        wq(k_w + l * wsq, p_wh + wsq,     p_wl + wsq,     wsq, HID);
        wq(v_w + l * wsq, p_wh + 2 * wsq, p_wl + 2 * wsq, wsq, HID);
        gemm_fp16<MODE_F32><<<dim3(S_LEN / BM, QKV_N / BN), 256, GEMM_SMEM>>>(
            p_x, p_wh, p_wl, nullptr, p_qkv, QKV_N, HID);

        rope_kernel<<<dim3(S_LEN, NH), 64>>>(p_qkv, pos_id);
        attn_kernel<<<dim3(NH, S_LEN / 64), 256>>>(p_qkv, p_x, pos_id);

        // O-proj + residual
        wq(o_w + l * wsq, p_wh, p_wl, wsq, HID);
        gemm_fp16<MODE_RES><<<dim3(S_LEN / BM, HID / BN), 256, GEMM_SMEM>>>(
            p_x, p_wh, p_wl, p_h, p_a, HID, HID);

        rmsnorm_h<<<S_LEN, 256>>>(p_a, post_ln_w + l * HID, p_x);

        // fused gate|up (rows interleaved: gate n->2n, up n->2n+1),
        // SwiGLU fused in epilogue -> fp16 activations into p_x2 (NOT p_x: A aliasing!)
        wq(gate_w + l * wsg, p_wh, p_wl, wsg, HID, 2, 0);
        wq(up_w   + l * wsg, p_wh, p_wl, wsg, HID, 2, 1);
        gemm_fp16<MODE_SWI><<<dim3(S_LEN / BM, GU_N / BN), 256, GEMM_SMEM>>>(
            p_x, p_wh, p_wl, nullptr, p_x2, GU_N, HID);

        // down-proj + residual
        wq(down_w + l * wsg, p_wh, p_wl, wsg, INTER);
        gemm_fp16<MODE_RES><<<dim3(S_LEN / BM, HID / BN), 256, GEMM_SMEM>>>(
            p_x2, p_wh, p_wl, p_a, p_h, HID, INTER);
    }

    rmsnorm_h<<<S_LEN, 256>>>(p_h, final_ln, p_x);
    wq(lm_head_w, p_wh, p_wl, (size_t)VOCAB * HID, HID);
    gemm_fp16<MODE_F32><<<dim3(S_LEN / BM, VOCAB / BN), 256, GEMM_SMEM>>>(
        p_x, p_wh, p_wl, nullptr, out, VOCAB, HID);
}